// round 2
// baseline (speedup 1.0000x reference)
#include <cuda_runtime.h>
#include <math.h>
#include <stdint.h>

#define IMGSZ   256
#define NPIX    65536
#define ZD      8
#define PED     64
#define HID     128
#define IN0     136          // ZD + 2*PED
#define TILE_R  128
#define NTHREADS 256

// Shared memory layout (floats):
//  sA : IN0*128  (activations, [k][row])
//  sW : IN0*128  (current layer weights, [k][n])
//  sB : HID*128  (activations ping-pong, [n][row])
#define SMEM_FLOATS (IN0*128 + IN0*128 + HID*128)   // 51200 floats = 204800 B

__global__ void ifv_zero_kernel(float4* __restrict__ out, int n4) {
    int i = blockIdx.x * blockDim.x + threadIdx.x;
    int stride = gridDim.x * blockDim.x;
    float4 z = make_float4(0.f, 0.f, 0.f, 0.f);
    for (; i < n4; i += stride) out[i] = z;
}

__global__ __launch_bounds__(NTHREADS, 1)
void ifv_main_kernel(const float* __restrict__ z,
                     const float* __restrict__ rotmat,
                     const float* __restrict__ pc,
                     const int*   __restrict__ midx,
                     const float* __restrict__ bg,
                     const float* __restrict__ w0, const float* __restrict__ b0,
                     const float* __restrict__ w1, const float* __restrict__ b1,
                     const float* __restrict__ w2, const float* __restrict__ b2,
                     const float* __restrict__ wout, const float* __restrict__ bout,
                     float* __restrict__ out, int M)
{
    extern __shared__ float smem[];
    float* sA = smem;                 // IN0*128
    float* sW = sA + IN0 * 128;       // IN0*128
    float* sB = sW + IN0 * 128;       // HID*128

    const int t  = threadIdx.x;
    const int b  = blockIdx.y;
    const int m0 = blockIdx.x * TILE_R;

    // Stage w0 into sW first — the global->smem loads are async-ish (in-flight
    // while we do the MUFU-heavy PE below), hiding the 68KB load latency.
    {
        const float4* s4 = reinterpret_cast<const float4*>(w0);
        float4* d4 = reinterpret_cast<float4*>(sW);
        #pragma unroll
        for (int i = t; i < (IN0 * 128) / 4; i += NTHREADS) d4[i] = s4[i];
    }

    // ---------------- Phase 1: positional encoding into sA ([k][row]) -------
    {
        const int row  = t & 127;
        const int half = t >> 7;          // 0 or 1: which 32 of the 64 freqs
        int m  = m0 + row;
        int mi = (m < M) ? m : (M - 1);
        int idx = midx[mi];
        float c0 = pc[idx * 3 + 0];
        float c1 = pc[idx * 3 + 1];
        float c2 = pc[idx * 3 + 2];
        const float* rm = rotmat + b * 9;
        // sel[d] = sum_c coords[c] * rm[c][d]
        float s0 = c0 * rm[0] + c1 * rm[3] + c2 * rm[6];
        float s1 = c0 * rm[1] + c1 * rm[4] + c2 * rm[7];
        float s2 = c0 * rm[2] + c1 * rm[5] + c2 * rm[8];

        if (half == 0) {
            #pragma unroll
            for (int k = 0; k < ZD; ++k)
                sA[k * 128 + row] = z[b * ZD + k];
        }

        const float TWOPI    = 6.28318530717958647692f;
        const float INV2PI   = 0.15915494309189533577f;
        const float TWOPI_HI = 6.28318548202514648f;   // float(2*pi)
        const float TWOPI_LO = -1.74845561e-07f;       // 2*pi - TWOPI_HI

        int p0 = half * 32;
        #pragma unroll 4
        for (int p = p0; p < p0 + 32; ++p) {
            float dotv = s0 * bg[p] + s1 * bg[64 + p] + s2 * bg[128 + p];
            float proj = TWOPI * dotv;
            // Cody-Waite reduction so sin/cos stay accurate even w/ fast-math
            float nn = rintf(proj * INV2PI);
            float r  = fmaf(nn, -TWOPI_HI, proj);
            r        = fmaf(nn, -TWOPI_LO, r);
            float sv, cv;
            sincosf(r, &sv, &cv);
            sA[(ZD + p) * 128 + row]       = sv;   // sin part: dims 8..71
            sA[(ZD + 64 + p) * 128 + row]  = cv;   // cos part: dims 72..135
        }
    }
    __syncthreads();

    // GEMM thread mapping: lane covers 32 consecutive rows (conflict-free),
    // warp id selects a 16-wide column strip (weights broadcast).
    const int lane = t & 31;
    const int n0   = (t >> 5) * 16;

    // ---------------- Layer 0: sB = relu(sA^T @ w0 + b0), K = 136 -----------
    {
        float acc[4][16];
        #pragma unroll
        for (int i = 0; i < 4; ++i)
            #pragma unroll
            for (int j = 0; j < 16; ++j) acc[i][j] = 0.f;

        #pragma unroll 4
        for (int k = 0; k < IN0; ++k) {
            const float* ak = sA + k * 128;
            float a0 = ak[lane];
            float a1 = ak[lane + 32];
            float a2 = ak[lane + 64];
            float a3 = ak[lane + 96];
            const float* wk = sW + k * 128 + n0;
            float4 wA = *reinterpret_cast<const float4*>(wk + 0);
            float4 wB = *reinterpret_cast<const float4*>(wk + 4);
            float4 wC = *reinterpret_cast<const float4*>(wk + 8);
            float4 wD = *reinterpret_cast<const float4*>(wk + 12);
            float wr[16] = {wA.x, wA.y, wA.z, wA.w, wB.x, wB.y, wB.z, wB.w,
                            wC.x, wC.y, wC.z, wC.w, wD.x, wD.y, wD.z, wD.w};
            #pragma unroll
            for (int j = 0; j < 16; ++j) {
                acc[0][j] = fmaf(a0, wr[j], acc[0][j]);
                acc[1][j] = fmaf(a1, wr[j], acc[1][j]);
                acc[2][j] = fmaf(a2, wr[j], acc[2][j]);
                acc[3][j] = fmaf(a3, wr[j], acc[3][j]);
            }
        }
        #pragma unroll
        for (int j = 0; j < 16; ++j) {
            float bb = b0[n0 + j];
            #pragma unroll
            for (int i = 0; i < 4; ++i) {
                float v = acc[i][j] + bb;
                sB[(n0 + j) * 128 + lane + 32 * i] = fmaxf(v, 0.f);
            }
        }
    }
    __syncthreads();

    // Load w1 into sW (16384 floats)
    {
        const float4* s4 = reinterpret_cast<const float4*>(w1);
        float4* d4 = reinterpret_cast<float4*>(sW);
        #pragma unroll
        for (int i = t; i < (HID * 128) / 4; i += NTHREADS) d4[i] = s4[i];
    }
    __syncthreads();

    // ---------------- Layer 1: sA = relu(sB^T @ w1 + b1), K = 128 -----------
    {
        float acc[4][16];
        #pragma unroll
        for (int i = 0; i < 4; ++i)
            #pragma unroll
            for (int j = 0; j < 16; ++j) acc[i][j] = 0.f;

        #pragma unroll 4
        for (int k = 0; k < HID; ++k) {
            const float* ak = sB + k * 128;
            float a0 = ak[lane];
            float a1 = ak[lane + 32];
            float a2 = ak[lane + 64];
            float a3 = ak[lane + 96];
            const float* wk = sW + k * 128 + n0;
            float4 wA = *reinterpret_cast<const float4*>(wk + 0);
            float4 wB = *reinterpret_cast<const float4*>(wk + 4);
            float4 wC = *reinterpret_cast<const float4*>(wk + 8);
            float4 wD = *reinterpret_cast<const float4*>(wk + 12);
            float wr[16] = {wA.x, wA.y, wA.z, wA.w, wB.x, wB.y, wB.z, wB.w,
                            wC.x, wC.y, wC.z, wC.w, wD.x, wD.y, wD.z, wD.w};
            #pragma unroll
            for (int j = 0; j < 16; ++j) {
                acc[0][j] = fmaf(a0, wr[j], acc[0][j]);
                acc[1][j] = fmaf(a1, wr[j], acc[1][j]);
                acc[2][j] = fmaf(a2, wr[j], acc[2][j]);
                acc[3][j] = fmaf(a3, wr[j], acc[3][j]);
            }
        }
        #pragma unroll
        for (int j = 0; j < 16; ++j) {
            float bb = b1[n0 + j];
            #pragma unroll
            for (int i = 0; i < 4; ++i) {
                float v = acc[i][j] + bb;
                sA[(n0 + j) * 128 + lane + 32 * i] = fmaxf(v, 0.f);
            }
        }
    }
    __syncthreads();

    // Load w2 into sW
    {
        const float4* s4 = reinterpret_cast<const float4*>(w2);
        float4* d4 = reinterpret_cast<float4*>(sW);
        #pragma unroll
        for (int i = t; i < (HID * 128) / 4; i += NTHREADS) d4[i] = s4[i];
    }
    __syncthreads();

    // ---------------- Layer 2: sB = relu(sA^T @ w2 + b2), K = 128 -----------
    {
        float acc[4][16];
        #pragma unroll
        for (int i = 0; i < 4; ++i)
            #pragma unroll
            for (int j = 0; j < 16; ++j) acc[i][j] = 0.f;

        #pragma unroll 4
        for (int k = 0; k < HID; ++k) {
            const float* ak = sA + k * 128;
            float a0 = ak[lane];
            float a1 = ak[lane + 32];
            float a2 = ak[lane + 64];
            float a3 = ak[lane + 96];
            const float* wk = sW + k * 128 + n0;
            float4 wA = *reinterpret_cast<const float4*>(wk + 0);
            float4 wB = *reinterpret_cast<const float4*>(wk + 4);
            float4 wC = *reinterpret_cast<const float4*>(wk + 8);
            float4 wD = *reinterpret_cast<const float4*>(wk + 12);
            float wr[16] = {wA.x, wA.y, wA.z, wA.w, wB.x, wB.y, wB.z, wB.w,
                            wC.x, wC.y, wC.z, wC.w, wD.x, wD.y, wD.z, wD.w};
            #pragma unroll
            for (int j = 0; j < 16; ++j) {
                acc[0][j] = fmaf(a0, wr[j], acc[0][j]);
                acc[1][j] = fmaf(a1, wr[j], acc[1][j]);
                acc[2][j] = fmaf(a2, wr[j], acc[2][j]);
                acc[3][j] = fmaf(a3, wr[j], acc[3][j]);
            }
        }
        #pragma unroll
        for (int j = 0; j < 16; ++j) {
            float bb = b2[n0 + j];
            #pragma unroll
            for (int i = 0; i < 4; ++i) {
                float v = acc[i][j] + bb;
                sB[(n0 + j) * 128 + lane + 32 * i] = fmaxf(v, 0.f);
            }
        }
    }
    __syncthreads();

    // ---------------- Output layer: 2-wide, scatter to grid -----------------
    if (t < 128) {
        int m = m0 + t;
        if (m < M) {
            float a0 = bout[0];
            float a1 = bout[1];
            #pragma unroll 4
            for (int n = 0; n < HID; ++n) {
                float h = sB[n * 128 + t];
                a0 = fmaf(h, wout[n * 2 + 0], a0);
                a1 = fmaf(h, wout[n * 2 + 1], a1);
            }
            int idx = midx[m];
            float2* o = reinterpret_cast<float2*>(out + ((size_t)b * NPIX + idx) * 2);
            *o = make_float2(a0, a1);
        }
    }
}

extern "C" void kernel_launch(void* const* d_in, const int* in_sizes, int n_in,
                              void* d_out, int out_size)
{
    const float* z      = (const float*)d_in[0];
    const float* rotmat = (const float*)d_in[1];
    const float* pc     = (const float*)d_in[2];
    const int*   midx   = (const int*)  d_in[3];
    const float* bg     = (const float*)d_in[4];
    const float* w0     = (const float*)d_in[5];
    const float* b0     = (const float*)d_in[6];
    const float* w1     = (const float*)d_in[7];
    const float* b1     = (const float*)d_in[8];
    const float* w2     = (const float*)d_in[9];
    const float* b2     = (const float*)d_in[10];
    const float* wout   = (const float*)d_in[11];
    const float* bout   = (const float*)d_in[12];
    float* out = (float*)d_out;

    const int M = in_sizes[3];
    const int B = in_sizes[0] / ZD;     // z is (B, 8)

    // 1) zero the whole output (poisoned, and only masked pixels get written)
    {
        int n4 = out_size / 4;
        int blocks = (n4 + 255) / 256;
        if (blocks > 2048) blocks = 2048;
        ifv_zero_kernel<<<blocks, 256>>>((float4*)out, n4);
    }

    // 2) fused PE + MLP + scatter
    static bool attr_done = false;
    if (!attr_done) {
        cudaFuncSetAttribute(ifv_main_kernel,
                             cudaFuncAttributeMaxDynamicSharedMemorySize,
                             SMEM_FLOATS * sizeof(float));
        attr_done = true;
    }
    dim3 grid((M + TILE_R - 1) / TILE_R, B);
    ifv_main_kernel<<<grid, NTHREADS, SMEM_FLOATS * sizeof(float)>>>(
        z, rotmat, pc, midx, bg, w0, b0, w1, b1, w2, b2, wout, bout, out, M);
}

// round 4
// speedup vs baseline: 3.0136x; 3.0136x over previous
#include <cuda_runtime.h>
#include <math.h>
#include <stdint.h>

#define ZD      8
#define HID     128
#define NPIX    65536
#define TILE_R  64
#define NTHREADS 256
#define GRID_P  148

// ---------------- SMEM byte offsets ----------------------------------------
#define OFF_W0   0          // 128x128 tf32 (w0 rows 8..135, [n][k] swizzled)
#define OFF_W1   65536
#define OFF_W2   131072
#define OFF_A    196608     // 64x128 activations ([row][k] swizzled)
#define OFF_ZB   229376     // 128 f32: b0 + z@w0[0:8]
#define OFF_B1   229888
#define OFF_B2   230400
#define OFF_WOUT 230912     // 128 float2
#define OFF_BOUT 231936     // 2 f32
#define SMEM_BYTES 231944

// word-index swizzle: elem (r, k) of a 128-wide row-major array
#define SWIX(r, k) ((r) * 128 + ((k) ^ (((r) & 7) << 2)))

__device__ __forceinline__ uint32_t f2tf32(float f) {
    uint32_t u;
    asm("cvt.rna.tf32.f32 %0, %1;" : "=r"(u) : "f"(f));
    return u;
}

__device__ __forceinline__ void mma_tf32(float c[4],
                                         uint32_t a0, uint32_t a1, uint32_t a2, uint32_t a3,
                                         uint32_t b0, uint32_t b1) {
    asm volatile("mma.sync.aligned.m16n8k8.row.col.f32.tf32.tf32.f32 "
                 "{%0,%1,%2,%3}, {%4,%5,%6,%7}, {%8,%9}, {%0,%1,%2,%3};"
                 : "+f"(c[0]), "+f"(c[1]), "+f"(c[2]), "+f"(c[3])
                 : "r"(a0), "r"(a1), "r"(a2), "r"(a3), "r"(b0), "r"(b1));
}

// 64x128 (rows) x 128x128 (weights) -> acc[2][4][4] per warp (warp tile 32x32)
__device__ __forceinline__ void gemm64(const uint32_t* __restrict__ sAw,
                                       const uint32_t* __restrict__ sW,
                                       float acc[2][4][4],
                                       int mi, int ni, int g, int tig) {
    const uint32_t rA0 = (uint32_t)(mi * 32 + g) * 128;   // rows r0, r0+8 at +1024
    const uint32_t rA1 = rA0 + 16 * 128;                  // mt=1 strip
    const uint32_t nb  = (uint32_t)(ni * 32 + g) * 128;   // ntile adds nt*8*128
    const uint32_t gsw = (uint32_t)g << 2;

    #pragma unroll
    for (int ks = 0; ks < 16; ++ks) {
        uint32_t kx  = ((uint32_t)(ks * 8 + tig)) ^ gsw;
        uint32_t kx2 = kx ^ 4u;
        uint32_t a00 = sAw[rA0 + kx],        a01 = sAw[rA0 + 1024 + kx];
        uint32_t a02 = sAw[rA0 + kx2],       a03 = sAw[rA0 + 1024 + kx2];
        uint32_t a10 = sAw[rA1 + kx],        a11 = sAw[rA1 + 1024 + kx];
        uint32_t a12 = sAw[rA1 + kx2],       a13 = sAw[rA1 + 1024 + kx2];
        #pragma unroll
        for (int nt = 0; nt < 4; ++nt) {
            uint32_t bo = nb + (uint32_t)nt * 1024;
            uint32_t b0 = sW[bo + kx];
            uint32_t b1 = sW[bo + kx2];
            mma_tf32(acc[0][nt], a00, a01, a02, a03, b0, b1);
            mma_tf32(acc[1][nt], a10, a11, a12, a13, b0, b1);
        }
    }
}

// bias + relu, write back into sA (tf32 if cvt, else raw f32 bits)
__device__ __forceinline__ void epi_store(uint32_t* __restrict__ sAw,
                                          const float* __restrict__ bias,
                                          float acc[2][4][4],
                                          int mi, int ni, int g, int tig, bool cvt) {
    const uint32_t gsw = (uint32_t)g << 2;
    #pragma unroll
    for (int mt = 0; mt < 2; ++mt) {
        uint32_t r0 = (uint32_t)(mi * 32 + mt * 16 + g);
        #pragma unroll
        for (int nt = 0; nt < 4; ++nt) {
            int cB = ni * 32 + nt * 8 + 2 * tig;
            float bb0 = bias[cB], bb1 = bias[cB + 1];
            float v00 = fmaxf(acc[mt][nt][0] + bb0, 0.f);
            float v01 = fmaxf(acc[mt][nt][1] + bb1, 0.f);
            float v10 = fmaxf(acc[mt][nt][2] + bb0, 0.f);
            float v11 = fmaxf(acc[mt][nt][3] + bb1, 0.f);
            uint32_t i0 = r0 * 128 + ((uint32_t)cB ^ gsw);
            uint32_t i1 = i0 + 1024;
            if (cvt) {
                *reinterpret_cast<uint2*>(sAw + i0) = make_uint2(f2tf32(v00), f2tf32(v01));
                *reinterpret_cast<uint2*>(sAw + i1) = make_uint2(f2tf32(v10), f2tf32(v11));
            } else {
                *reinterpret_cast<float2*>(sAw + i0) = make_float2(v00, v01);
                *reinterpret_cast<float2*>(sAw + i1) = make_float2(v10, v11);
            }
        }
    }
}

__global__ void ifv_zero_kernel(float4* __restrict__ out, int n4) {
    int i = blockIdx.x * blockDim.x + threadIdx.x;
    int stride = gridDim.x * blockDim.x;
    float4 zv = make_float4(0.f, 0.f, 0.f, 0.f);
    for (; i < n4; i += stride) out[i] = zv;
}

__global__ __launch_bounds__(NTHREADS, 1)
void ifv_mma_kernel(const float* __restrict__ z,
                    const float* __restrict__ rotmat,
                    const float* __restrict__ pc,
                    const int*   __restrict__ midx,
                    const float* __restrict__ bg,
                    const float* __restrict__ w0, const float* __restrict__ b0,
                    const float* __restrict__ w1, const float* __restrict__ b1,
                    const float* __restrict__ w2, const float* __restrict__ b2,
                    const float* __restrict__ wout, const float* __restrict__ bout,
                    float* __restrict__ out, int M, int tiles, int total)
{
    extern __shared__ char smem[];
    uint32_t* sW0 = (uint32_t*)(smem + OFF_W0);
    uint32_t* sW1 = (uint32_t*)(smem + OFF_W1);
    uint32_t* sW2 = (uint32_t*)(smem + OFF_W2);
    uint32_t* sA  = (uint32_t*)(smem + OFF_A);
    float*    zb  = (float*)(smem + OFF_ZB);
    float*    sB1 = (float*)(smem + OFF_B1);
    float*    sB2 = (float*)(smem + OFF_B2);
    float2*   sWo = (float2*)(smem + OFF_WOUT);
    float*    sBo = (float*)(smem + OFF_BOUT);

    const int t    = threadIdx.x;
    const int wid  = t >> 5;
    const int lane = t & 31;
    const int g    = lane >> 2;
    const int tig  = lane & 3;
    const int mi   = wid >> 2;     // 0..1
    const int ni   = wid & 3;      // 0..3

    // ---------------- one-time staging: weights (tf32, [n][k] swizzled) ----
    #pragma unroll 4
    for (int i = t; i < HID * HID; i += NTHREADS) {
        int k = i >> 7, n = i & 127;
        sW0[SWIX(n, k)] = f2tf32(w0[(k + ZD) * HID + n]);   // rows 8..135
        sW1[SWIX(n, k)] = f2tf32(w1[k * HID + n]);
        sW2[SWIX(n, k)] = f2tf32(w2[k * HID + n]);
    }
    if (t < HID) {
        sB1[t] = b1[t];
        sB2[t] = b2[t];
        sWo[t] = make_float2(wout[t * 2 + 0], wout[t * 2 + 1]);
        if (t < 2) sBo[t] = bout[t];
    }
    __syncthreads();

    int unit = blockIdx.x;
    while (unit < total) {
        const int b  = unit / tiles;
        const int m0 = (unit - b * tiles) * TILE_R;

        // ---------- zb: b0 + z @ w0[0:8] (fp32 exact), threads 0..127 ------
        if (t < HID) {
            float acc = b0[t];
            #pragma unroll
            for (int k = 0; k < ZD; ++k)
                acc = fmaf(z[b * ZD + k], w0[k * HID + t], acc);
            zb[t] = acc;
        }

        // ---------- PE: rows t>>2, freq quarter t&3 ------------------------
        {
            const int row = t >> 2;        // 0..63
            const int q   = t & 3;         // 16 freqs each
            int m  = m0 + row;
            int mi2 = (m < M) ? m : (M - 1);
            int idx = midx[mi2];
            float c0 = pc[idx * 3 + 0];
            float c1 = pc[idx * 3 + 1];
            float c2 = pc[idx * 3 + 2];
            const float* rm = rotmat + b * 9;
            float s0 = c0 * rm[0] + c1 * rm[3] + c2 * rm[6];
            float s1 = c0 * rm[1] + c1 * rm[4] + c2 * rm[7];
            float s2 = c0 * rm[2] + c1 * rm[5] + c2 * rm[8];

            const float TWOPI    = 6.28318530717958647692f;
            const float INV2PI   = 0.15915494309189533577f;
            const float TWOPI_HI = 6.28318548202514648f;
            const float TWOPI_LO = -1.74845561e-07f;
            const uint32_t rsw = (uint32_t)(row & 7) << 2;
            const uint32_t rbase = (uint32_t)row * 128;

            #pragma unroll 4
            for (int j = 0; j < 16; ++j) {
                int p = q * 16 + j;
                float dotv = s0 * bg[p] + s1 * bg[64 + p] + s2 * bg[128 + p];
                float proj = TWOPI * dotv;
                float nn = rintf(proj * INV2PI);
                float r  = fmaf(nn, -TWOPI_HI, proj);
                r        = fmaf(nn, -TWOPI_LO, r);
                float sv, cv;
                sincosf(r, &sv, &cv);
                sA[rbase + ((uint32_t)p ^ rsw)]        = f2tf32(sv);   // k = 0..63
                sA[rbase + ((uint32_t)(64 + p) ^ rsw)] = f2tf32(cv);   // k = 64..127
            }
        }
        __syncthreads();

        float acc[2][4][4];

        // ---------------- layer 0 (bias = zb) ------------------------------
        #pragma unroll
        for (int a = 0; a < 2; ++a)
            #pragma unroll
            for (int c = 0; c < 4; ++c)
                #pragma unroll
                for (int d = 0; d < 4; ++d) acc[a][c][d] = 0.f;
        gemm64(sA, sW0, acc, mi, ni, g, tig);
        __syncthreads();
        epi_store(sA, zb, acc, mi, ni, g, tig, true);
        __syncthreads();

        // ---------------- layer 1 ------------------------------------------
        #pragma unroll
        for (int a = 0; a < 2; ++a)
            #pragma unroll
            for (int c = 0; c < 4; ++c)
                #pragma unroll
                for (int d = 0; d < 4; ++d) acc[a][c][d] = 0.f;
        gemm64(sA, sW1, acc, mi, ni, g, tig);
        __syncthreads();
        epi_store(sA, sB1, acc, mi, ni, g, tig, true);
        __syncthreads();

        // ---------------- layer 2 (store raw fp32 h) -----------------------
        #pragma unroll
        for (int a = 0; a < 2; ++a)
            #pragma unroll
            for (int c = 0; c < 4; ++c)
                #pragma unroll
                for (int d = 0; d < 4; ++d) acc[a][c][d] = 0.f;
        gemm64(sA, sW2, acc, mi, ni, g, tig);
        __syncthreads();
        epi_store(sA, sB2, acc, mi, ni, g, tig, false);
        __syncthreads();

        // ---------------- output layer: h(128) -> 2, scatter ---------------
        {
            const int row  = t >> 2;       // 0..63
            const int part = t & 3;
            const uint32_t rsw = (uint32_t)(row & 7) << 2;
            const uint32_t rbase = (uint32_t)row * 128;
            float s0 = 0.f, s1 = 0.f;
            #pragma unroll 8
            for (int i = 0; i < 32; ++i) {
                int c = part + i * 4;      // interleaved: conflict-free
                float h = __uint_as_float(sA[rbase + ((uint32_t)c ^ rsw)]);
                float2 wv = sWo[c];
                s0 = fmaf(h, wv.x, s0);
                s1 = fmaf(h, wv.y, s1);
            }
            s0 += __shfl_xor_sync(0xFFFFFFFF, s0, 1);
            s0 += __shfl_xor_sync(0xFFFFFFFF, s0, 2);
            s1 += __shfl_xor_sync(0xFFFFFFFF, s1, 1);
            s1 += __shfl_xor_sync(0xFFFFFFFF, s1, 2);
            int m = m0 + row;
            if (part == 0 && m < M) {
                int idx = midx[m];
                float2* o = reinterpret_cast<float2*>(out + ((size_t)b * NPIX + idx) * 2);
                *o = make_float2(s0 + sBo[0], s1 + sBo[1]);
            }
        }
        __syncthreads();   // sA reused by next tile's PE

        unit += gridDim.x;
    }
}

extern "C" void kernel_launch(void* const* d_in, const int* in_sizes, int n_in,
                              void* d_out, int out_size)
{
    const float* z      = (const float*)d_in[0];
    const float* rotmat = (const float*)d_in[1];
    const float* pc     = (const float*)d_in[2];
    const int*   midx   = (const int*)  d_in[3];
    const float* bg     = (const float*)d_in[4];
    const float* w0     = (const float*)d_in[5];
    const float* b0     = (const float*)d_in[6];
    const float* w1     = (const float*)d_in[7];
    const float* b1     = (const float*)d_in[8];
    const float* w2     = (const float*)d_in[9];
    const float* b2     = (const float*)d_in[10];
    const float* wout   = (const float*)d_in[11];
    const float* bout   = (const float*)d_in[12];
    float* out = (float*)d_out;

    const int M = in_sizes[3];
    const int B = in_sizes[0] / ZD;
    const int tiles = (M + TILE_R - 1) / TILE_R;
    const int total = B * tiles;

    // zero whole output (poisoned; only masked pixels are written)
    {
        int n4 = out_size / 4;
        int blocks = (n4 + 255) / 256;
        if (blocks > 2048) blocks = 2048;
        ifv_zero_kernel<<<blocks, 256>>>((float4*)out, n4);
    }

    static bool attr_done = false;
    if (!attr_done) {
        cudaFuncSetAttribute(ifv_mma_kernel,
                             cudaFuncAttributeMaxDynamicSharedMemorySize, SMEM_BYTES);
        attr_done = true;
    }
    int grid = total < GRID_P ? total : GRID_P;
    ifv_mma_kernel<<<grid, NTHREADS, SMEM_BYTES>>>(
        z, rotmat, pc, midx, bg, w0, b0, w1, b1, w2, b2, wout, bout,
        out, M, tiles, total);
}

// round 5
// speedup vs baseline: 4.0041x; 1.3287x over previous
#include <cuda_runtime.h>
#include <cuda_fp16.h>
#include <math.h>
#include <stdint.h>

#define ZD      8
#define HID     128
#define NPIX    65536
#define TILE_R  96
#define NTHREADS 384
#define GRID_P  148

// ---------------- SMEM byte offsets ----------------------------------------
// weights as fp16 [n][k] swizzled; A as fp16 [row][k] swizzled
#define OFF_W0   0            // 128x128 half = 32768
#define OFF_W1   32768
#define OFF_W2   65536
#define OFF_A    98304        // 96x128 half = 24576
#define OFF_ZB   122880       // 128 f32 (b0 + z@w0[0:8])
#define OFF_B1   123392       // 128 f32
#define OFF_B2   123904       // 128 f32
#define OFF_WOUT 124416       // 128 float2
#define SMEM_BYTES 125440

// half-index swizzle: element (r,k) of [r][128] half array; 16B granules (8 halves)
#define HSW(r, k) ((r) * 128 + (((((k) >> 3) ^ ((r) & 7)) << 3) | ((k) & 7)))

__device__ __forceinline__ uint32_t smem_u32(const void* p) {
    uint32_t a;
    asm("{ .reg .u64 t; cvta.to.shared.u64 t, %1; cvt.u32.u64 %0, t; }" : "=r"(a) : "l"(p));
    return a;
}
__device__ __forceinline__ void ldsm4(uint32_t& r0, uint32_t& r1, uint32_t& r2, uint32_t& r3,
                                      uint32_t addr) {
    asm volatile("ldmatrix.sync.aligned.m8n8.x4.shared.b16 {%0,%1,%2,%3}, [%4];"
                 : "=r"(r0), "=r"(r1), "=r"(r2), "=r"(r3) : "r"(addr));
}
__device__ __forceinline__ void mma_f16(float c[4],
                                        uint32_t a0, uint32_t a1, uint32_t a2, uint32_t a3,
                                        uint32_t b0, uint32_t b1) {
    asm volatile("mma.sync.aligned.m16n8k16.row.col.f32.f16.f16.f32 "
                 "{%0,%1,%2,%3}, {%4,%5,%6,%7}, {%8,%9}, {%0,%1,%2,%3};"
                 : "+f"(c[0]), "+f"(c[1]), "+f"(c[2]), "+f"(c[3])
                 : "r"(a0), "r"(a1), "r"(a2), "r"(a3), "r"(b0), "r"(b1));
}

__global__ void ifv_zero_kernel(float4* __restrict__ out, int n4) {
    int i = blockIdx.x * blockDim.x + threadIdx.x;
    int stride = gridDim.x * blockDim.x;
    float4 zv = make_float4(0.f, 0.f, 0.f, 0.f);
    for (; i < n4; i += stride) out[i] = zv;
}

__global__ __launch_bounds__(NTHREADS, 1)
void ifv_h16_kernel(const float* __restrict__ z,
                    const float* __restrict__ rotmat,
                    const float* __restrict__ pc,
                    const int*   __restrict__ midx,
                    const float* __restrict__ bg,
                    const float* __restrict__ w0, const float* __restrict__ b0,
                    const float* __restrict__ w1, const float* __restrict__ b1,
                    const float* __restrict__ w2, const float* __restrict__ b2,
                    const float* __restrict__ wout, const float* __restrict__ bout,
                    float* __restrict__ out, int M, int tiles, int total)
{
    extern __shared__ char smem[];
    __half*  sW0 = (__half*)(smem + OFF_W0);
    __half*  sW1 = (__half*)(smem + OFF_W1);
    __half*  sW2 = (__half*)(smem + OFF_W2);
    __half*  sAh = (__half*)(smem + OFF_A);
    float*   zb  = (float*)(smem + OFF_ZB);
    float*   sB1 = (float*)(smem + OFF_B1);
    float*   sB2 = (float*)(smem + OFF_B2);
    float2*  sWo = (float2*)(smem + OFF_WOUT);

    const uint32_t sbase = smem_u32(smem);
    const uint32_t aBase = sbase + OFF_A;

    const int t    = threadIdx.x;
    const int wid  = t >> 5;
    const int lane = t & 31;
    const int mi   = wid >> 2;     // 0..2  (32-row strip)
    const int ni   = wid & 3;      // 0..3  (32-col strip)

    // ---------------- one-time weight staging (fp16, [n][k] swizzled) ------
    for (int i = t; i < HID * HID; i += NTHREADS) {
        int k = i >> 7, n = i & 127;
        int sw = HSW(n, k);
        sW0[sw] = __float2half(w0[(k + ZD) * HID + n]);   // rows 8..135 (z folded)
        sW1[sw] = __float2half(w1[k * HID + n]);
        sW2[sw] = __float2half(w2[k * HID + n]);
    }
    if (t < HID) {
        sB1[t] = b1[t];
        sB2[t] = b2[t];
        sWo[t] = make_float2(wout[t * 2 + 0], wout[t * 2 + 1]);
    }
    __syncthreads();

    // ---------------- per-thread ldmatrix address precompute ----------------
    // A: sel = lane>>3; row = mi*32 + mt*16 + (sel&1)*8 + (lane&7); kg += sel>>1
    // B: n = ni*32 + ntp*16 + (sel>>1)*8 + (lane&7); kg += sel&1
    const uint32_t aSelKg = (uint32_t)(lane >> 4);          // sel>>1
    const uint32_t bSelKg = (uint32_t)((lane >> 3) & 1);    // sel&1
    uint32_t aRow[2], bRowN[2];
    #pragma unroll
    for (int mt = 0; mt < 2; ++mt)
        aRow[mt] = (uint32_t)(mi * 32 + mt * 16 + (((lane >> 3) & 1) << 3) + (lane & 7));
    #pragma unroll
    for (int ntp = 0; ntp < 2; ++ntp)
        bRowN[ntp] = (uint32_t)(ni * 32 + ntp * 16 + ((lane >> 4) << 3) + (lane & 7));

    int unit = blockIdx.x;
    while (unit < total) {
        const int b  = unit / tiles;
        const int m0 = (unit - b * tiles) * TILE_R;

        // -------- zb = b0 + z @ w0[0:8]  (fp32 exact) -----------------------
        if (t < HID) {
            float acc = b0[t];
            #pragma unroll
            for (int k = 0; k < ZD; ++k)
                acc = fmaf(z[b * ZD + k], w0[k * HID + t], acc);
            zb[t] = acc;
        }

        // -------- PE: row = t>>2 (0..95), quarter q = t&3 -------------------
        {
            const int row = t >> 2;
            const int q   = t & 3;
            int m  = m0 + row;
            int mc = (m < M) ? m : (M - 1);
            int idx = midx[mc];
            float c0 = pc[idx * 3 + 0];
            float c1 = pc[idx * 3 + 1];
            float c2 = pc[idx * 3 + 2];
            const float* rm = rotmat + b * 9;
            float s0 = c0 * rm[0] + c1 * rm[3] + c2 * rm[6];
            float s1 = c0 * rm[1] + c1 * rm[4] + c2 * rm[7];
            float s2 = c0 * rm[2] + c1 * rm[5] + c2 * rm[8];

            const float TWOPI    = 6.28318530717958647692f;
            const float INV2PI   = 0.15915494309189533577f;
            const float TWOPI_HI = 6.28318548202514648f;
            const float TWOPI_LO = -1.74845561e-07f;

            #pragma unroll 4
            for (int j = 0; j < 16; ++j) {
                int p = q * 16 + j;
                float dotv = s0 * bg[p] + s1 * bg[64 + p] + s2 * bg[128 + p];
                float proj = TWOPI * dotv;
                float nn = rintf(proj * INV2PI);
                float r  = fmaf(nn, -TWOPI_HI, proj);
                r        = fmaf(nn, -TWOPI_LO, r);
                float sv, cv;
                sincosf(r, &sv, &cv);
                sAh[HSW(row, p)]      = __float2half(sv);
                sAh[HSW(row, 64 + p)] = __float2half(cv);
            }
        }
        __syncthreads();

        float acc[2][4][4];
        const float* biases[3] = { zb, sB1, sB2 };
        const uint32_t wb[3] = { sbase + OFF_W0, sbase + OFF_W1, sbase + OFF_W2 };

        #pragma unroll
        for (int layer = 0; layer < 3; ++layer) {
            #pragma unroll
            for (int a = 0; a < 2; ++a)
                #pragma unroll
                for (int c = 0; c < 4; ++c)
                    #pragma unroll
                    for (int d = 0; d < 4; ++d) acc[a][c][d] = 0.f;

            const uint32_t wBase = wb[layer];

            #pragma unroll
            for (int ks = 0; ks < 8; ++ks) {
                const uint32_t kg = (uint32_t)(ks * 2);
                uint32_t af[2][4];
                #pragma unroll
                for (int mt = 0; mt < 2; ++mt) {
                    uint32_t r = aRow[mt];
                    uint32_t ad = aBase + ((r * 16 + ((kg + aSelKg) ^ (r & 7))) << 4);
                    ldsm4(af[mt][0], af[mt][1], af[mt][2], af[mt][3], ad);
                }
                uint32_t bf[4][2];
                #pragma unroll
                for (int ntp = 0; ntp < 2; ++ntp) {
                    uint32_t n = bRowN[ntp];
                    uint32_t bd = wBase + ((n * 16 + ((kg + bSelKg) ^ (n & 7))) << 4);
                    uint32_t r0, r1, r2, r3;
                    ldsm4(r0, r1, r2, r3, bd);
                    bf[ntp * 2 + 0][0] = r0; bf[ntp * 2 + 0][1] = r1;
                    bf[ntp * 2 + 1][0] = r2; bf[ntp * 2 + 1][1] = r3;
                }
                #pragma unroll
                for (int mt = 0; mt < 2; ++mt)
                    #pragma unroll
                    for (int nt = 0; nt < 4; ++nt)
                        mma_f16(acc[mt][nt], af[mt][0], af[mt][1], af[mt][2], af[mt][3],
                                bf[nt][0], bf[nt][1]);
            }
            __syncthreads();   // all reads of sA done

            // epilogue: bias + relu -> fp16 back into sA
            const float* bias = biases[layer];
            #pragma unroll
            for (int mt = 0; mt < 2; ++mt) {
                int rowE = mi * 32 + mt * 16 + (lane >> 2);
                #pragma unroll
                for (int nt = 0; nt < 4; ++nt) {
                    int cB = ni * 32 + nt * 8 + 2 * (lane & 3);
                    float bb0 = bias[cB], bb1 = bias[cB + 1];
                    float v00 = fmaxf(acc[mt][nt][0] + bb0, 0.f);
                    float v01 = fmaxf(acc[mt][nt][1] + bb1, 0.f);
                    float v10 = fmaxf(acc[mt][nt][2] + bb0, 0.f);
                    float v11 = fmaxf(acc[mt][nt][3] + bb1, 0.f);
                    *reinterpret_cast<__half2*>(sAh + HSW(rowE, cB)) =
                        __floats2half2_rn(v00, v01);
                    *reinterpret_cast<__half2*>(sAh + HSW(rowE + 8, cB)) =
                        __floats2half2_rn(v10, v11);
                }
            }
            __syncthreads();   // writes visible before next layer / output
        }

        // -------- output: h(128) -> 2, shfl-reduce, scatter -----------------
        {
            const int row  = t >> 2;
            const int part = t & 3;
            float s0 = 0.f, s1 = 0.f;
            #pragma unroll 4
            for (int i = 0; i < 16; ++i) {
                int c = part * 32 + i * 2;
                __half2 h2 = *reinterpret_cast<const __half2*>(sAh + HSW(row, c));
                float2 hf = __half22float2(h2);
                float2 wv0 = sWo[c], wv1 = sWo[c + 1];
                s0 = fmaf(hf.x, wv0.x, fmaf(hf.y, wv1.x, s0));
                s1 = fmaf(hf.x, wv0.y, fmaf(hf.y, wv1.y, s1));
            }
            s0 += __shfl_xor_sync(0xFFFFFFFF, s0, 1);
            s0 += __shfl_xor_sync(0xFFFFFFFF, s0, 2);
            s1 += __shfl_xor_sync(0xFFFFFFFF, s1, 1);
            s1 += __shfl_xor_sync(0xFFFFFFFF, s1, 2);
            int m = m0 + row;
            if (part == 0 && m < M) {
                int idx = midx[m];
                float2* o = reinterpret_cast<float2*>(out + ((size_t)b * NPIX + idx) * 2);
                *o = make_float2(s0 + bout[0], s1 + bout[1]);
            }
        }
        __syncthreads();   // sA reused by next tile's PE

        unit += gridDim.x;
    }
}

extern "C" void kernel_launch(void* const* d_in, const int* in_sizes, int n_in,
                              void* d_out, int out_size)
{
    const float* z      = (const float*)d_in[0];
    const float* rotmat = (const float*)d_in[1];
    const float* pc     = (const float*)d_in[2];
    const int*   midx   = (const int*)  d_in[3];
    const float* bg     = (const float*)d_in[4];
    const float* w0     = (const float*)d_in[5];
    const float* b0     = (const float*)d_in[6];
    const float* w1     = (const float*)d_in[7];
    const float* b1     = (const float*)d_in[8];
    const float* w2     = (const float*)d_in[9];
    const float* b2     = (const float*)d_in[10];
    const float* wout   = (const float*)d_in[11];
    const float* bout   = (const float*)d_in[12];
    float* out = (float*)d_out;

    const int M = in_sizes[3];
    const int B = in_sizes[0] / ZD;
    const int tiles = (M + TILE_R - 1) / TILE_R;
    const int total = B * tiles;

    // zero whole output (poisoned; only masked pixels are written)
    {
        int n4 = out_size / 4;
        int blocks = (n4 + 255) / 256;
        if (blocks > 2048) blocks = 2048;
        ifv_zero_kernel<<<blocks, 256>>>((float4*)out, n4);
    }

    static bool attr_done = false;
    if (!attr_done) {
        cudaFuncSetAttribute(ifv_h16_kernel,
                             cudaFuncAttributeMaxDynamicSharedMemorySize, SMEM_BYTES);
        attr_done = true;
    }
    int grid = total < GRID_P ? total : GRID_P;
    ifv_h16_kernel<<<grid, NTHREADS, SMEM_BYTES>>>(
        z, rotmat, pc, midx, bg, w0, b0, w1, b1, w2, b2, wout, bout,
        out, M, tiles, total);
}

// round 6
// speedup vs baseline: 5.9267x; 1.4802x over previous
#include <cuda_runtime.h>
#include <cuda_fp16.h>
#include <math.h>
#include <stdint.h>

#define ZD      8
#define HID     128
#define NPIX    65536
#define TILE_R  128          // 8 warps x 16 rows
#define NTHREADS 256
#define GRID_P  148

// ---------------- SMEM byte offsets ----------------------------------------
#define OFF_W0   0            // 128x128 half [n][k] swizzled = 32768
#define OFF_W1   32768
#define OFF_W2   65536
#define OFF_ZB   98304        // 16 x 128 f32: b0 + z_b @ w0[0:8]
#define OFF_B1   106496       // 128 f32
#define OFF_B2   107008       // 128 f32
#define OFF_WOUT 107520       // 128 float2
#define SMEM_BYTES 108544

// half-index swizzle for weights: element (n,k) of [n][128]; 16B granules
#define HSW(n, k) ((n) * 128 + (((((k) >> 3) ^ ((n) & 7)) << 3) | ((k) & 7)))

__device__ __forceinline__ uint32_t smem_u32(const void* p) {
    uint32_t a;
    asm("{ .reg .u64 t; cvta.to.shared.u64 t, %1; cvt.u32.u64 %0, t; }" : "=r"(a) : "l"(p));
    return a;
}
__device__ __forceinline__ void ldsm4(uint32_t& r0, uint32_t& r1, uint32_t& r2, uint32_t& r3,
                                      uint32_t addr) {
    asm volatile("ldmatrix.sync.aligned.m8n8.x4.shared.b16 {%0,%1,%2,%3}, [%4];"
                 : "=r"(r0), "=r"(r1), "=r"(r2), "=r"(r3) : "r"(addr));
}
__device__ __forceinline__ void mma_f16(float c[4],
                                        uint32_t a0, uint32_t a1, uint32_t a2, uint32_t a3,
                                        uint32_t b0, uint32_t b1) {
    asm volatile("mma.sync.aligned.m16n8k16.row.col.f32.f16.f16.f32 "
                 "{%0,%1,%2,%3}, {%4,%5,%6,%7}, {%8,%9}, {%0,%1,%2,%3};"
                 : "+f"(c[0]), "+f"(c[1]), "+f"(c[2]), "+f"(c[3])
                 : "r"(a0), "r"(a1), "r"(a2), "r"(a3), "r"(b0), "r"(b1));
}
__device__ __forceinline__ uint32_t packh2(float a, float b) {
    __half2 h = __floats2half2_rn(a, b);
    return *reinterpret_cast<uint32_t*>(&h);
}

// one full layer: acc[16][4] = A(aF) @ W(128x128), per-warp 16x128 strip
__device__ __forceinline__ void layer_mma(const uint32_t aF[8][4], float acc[16][4],
                                          uint32_t wBase, uint32_t nLoc, uint32_t bSelKg) {
    #pragma unroll
    for (int nt = 0; nt < 16; ++nt)
        #pragma unroll
        for (int d = 0; d < 4; ++d) acc[nt][d] = 0.f;

    #pragma unroll
    for (int kt = 0; kt < 8; ++kt) {
        uint32_t bf[16][2];
        #pragma unroll
        for (int ng = 0; ng < 8; ++ng) {
            uint32_t n = (uint32_t)(ng * 16) + nLoc;
            uint32_t ad = wBase + n * 256 +
                          ((((uint32_t)(2 * kt) + bSelKg) ^ (n & 7)) << 4);
            ldsm4(bf[2 * ng][0], bf[2 * ng][1], bf[2 * ng + 1][0], bf[2 * ng + 1][1], ad);
        }
        #pragma unroll
        for (int nt = 0; nt < 16; ++nt)
            mma_f16(acc[nt], aF[kt][0], aF[kt][1], aF[kt][2], aF[kt][3],
                    bf[nt][0], bf[nt][1]);
    }
}

// bias + relu + pack: accumulator fragments -> next layer's A fragments
__device__ __forceinline__ void epi_pack(uint32_t aF[8][4], const float acc[16][4],
                                         const float* __restrict__ bias, int q) {
    #pragma unroll
    for (int kt = 0; kt < 8; ++kt) {
        int c0 = 16 * kt + 2 * q;
        float2 bA = *reinterpret_cast<const float2*>(bias + c0);
        float2 bB = *reinterpret_cast<const float2*>(bias + c0 + 8);
        aF[kt][0] = packh2(fmaxf(acc[2 * kt][0] + bA.x, 0.f),
                           fmaxf(acc[2 * kt][1] + bA.y, 0.f));
        aF[kt][1] = packh2(fmaxf(acc[2 * kt][2] + bA.x, 0.f),
                           fmaxf(acc[2 * kt][3] + bA.y, 0.f));
        aF[kt][2] = packh2(fmaxf(acc[2 * kt + 1][0] + bB.x, 0.f),
                           fmaxf(acc[2 * kt + 1][1] + bB.y, 0.f));
        aF[kt][3] = packh2(fmaxf(acc[2 * kt + 1][2] + bB.x, 0.f),
                           fmaxf(acc[2 * kt + 1][3] + bB.y, 0.f));
    }
}

__global__ void ifv_zero_kernel(float4* __restrict__ out, int n4) {
    int i = blockIdx.x * blockDim.x + threadIdx.x;
    int stride = gridDim.x * blockDim.x;
    float4 zv = make_float4(0.f, 0.f, 0.f, 0.f);
    for (; i < n4; i += stride) out[i] = zv;
}

__global__ __launch_bounds__(NTHREADS, 1)
void ifv_reg_kernel(const float* __restrict__ z,
                    const float* __restrict__ rotmat,
                    const float* __restrict__ pc,
                    const int*   __restrict__ midx,
                    const float* __restrict__ bg,
                    const float* __restrict__ w0, const float* __restrict__ b0,
                    const float* __restrict__ w1, const float* __restrict__ b1,
                    const float* __restrict__ w2, const float* __restrict__ b2,
                    const float* __restrict__ wout, const float* __restrict__ bout,
                    float* __restrict__ out, int M, int tiles, int total, int nimg)
{
    extern __shared__ char smem[];
    __half*  sW0 = (__half*)(smem + OFF_W0);
    __half*  sW1 = (__half*)(smem + OFF_W1);
    __half*  sW2 = (__half*)(smem + OFF_W2);
    float*   sZB = (float*)(smem + OFF_ZB);
    float*   sB1 = (float*)(smem + OFF_B1);
    float*   sB2 = (float*)(smem + OFF_B2);
    float2*  sWo = (float2*)(smem + OFF_WOUT);

    const uint32_t sbase = smem_u32(smem);
    const int t    = threadIdx.x;
    const int wid  = t >> 5;
    const int lane = t & 31;
    const int q    = lane & 3;
    const int rsub = lane >> 2;                  // 0..7

    // ---------------- one-time staging (weights fp16 [n][k] swizzled) ------
    for (int i = t; i < HID * HID; i += NTHREADS) {
        int k = i >> 7, n = i & 127;
        int sw = HSW(n, k);
        sW0[sw] = __float2half(w0[(k + ZD) * HID + n]);  // z rows folded into zb
        sW1[sw] = __float2half(w1[k * HID + n]);
        sW2[sw] = __float2half(w2[k * HID + n]);
    }
    // zb[b][c] = b0[c] + z[b] . w0[0:8][c]  for all images
    for (int i = t; i < nimg * HID; i += NTHREADS) {
        int bb = i >> 7, c = i & 127;
        float a = b0[c];
        #pragma unroll
        for (int k = 0; k < ZD; ++k)
            a = fmaf(z[bb * ZD + k], w0[k * HID + c], a);
        sZB[i] = a;
    }
    if (t < HID) {
        sB1[t] = b1[t];
        sB2[t] = b2[t];
        sWo[t] = make_float2(wout[t * 2 + 0], wout[t * 2 + 1]);
    }
    __syncthreads();   // the ONLY block barrier

    const uint32_t bSelKg = (uint32_t)((lane >> 3) & 1);
    const uint32_t nLoc   = (uint32_t)(((lane >> 4) << 3) + (lane & 7));
    const float bo0 = bout[0], bo1 = bout[1];

    const float TWOPI    = 6.28318530717958647692f;
    const float INV2PI   = 0.15915494309189533577f;
    const float TWOPI_HI = 6.28318548202514648f;
    const float TWOPI_LO = -1.74845561e-07f;

    int unit = blockIdx.x;
    while (unit < total) {
        const int b  = unit / tiles;
        const int m0 = (unit - b * tiles) * TILE_R + wid * 16;
        const int mr0 = m0 + rsub;
        const int mr1 = mr0 + 8;

        // ---------------- PE directly into A fragments ----------------------
        uint32_t aF[8][4];
        float s0[2], s1[2], s2[2];
        {
            const float* rm = rotmat + b * 9;
            float r00 = rm[0], r01 = rm[1], r02 = rm[2];
            float r10 = rm[3], r11 = rm[4], r12 = rm[5];
            float r20 = rm[6], r21 = rm[7], r22 = rm[8];
            #pragma unroll
            for (int rr = 0; rr < 2; ++rr) {
                int m  = rr == 0 ? mr0 : mr1;
                int mc = (m < M) ? m : (M - 1);
                int idx = midx[mc];
                float c0 = pc[idx * 3 + 0];
                float c1 = pc[idx * 3 + 1];
                float c2 = pc[idx * 3 + 2];
                s0[rr] = c0 * r00 + c1 * r10 + c2 * r20;
                s1[rr] = c0 * r01 + c1 * r11 + c2 * r21;
                s2[rr] = c0 * r02 + c1 * r12 + c2 * r22;
            }
        }
        #pragma unroll
        for (int j = 0; j < 8; ++j) {
            int p0 = 8 * j + 2 * q;
            float g00 = bg[p0],     g01 = bg[64 + p0],     g02 = bg[128 + p0];
            float g10 = bg[p0 + 1], g11 = bg[64 + p0 + 1], g12 = bg[128 + p0 + 1];
            int slotL = (j & 1) * 2;      // k-low slots for even j, k-high for odd
            #pragma unroll
            for (int rr = 0; rr < 2; ++rr) {
                float d0 = s0[rr] * g00 + s1[rr] * g01 + s2[rr] * g02;
                float d1 = s0[rr] * g10 + s1[rr] * g11 + s2[rr] * g12;
                float pj0 = TWOPI * d0, pj1 = TWOPI * d1;
                float n0 = rintf(pj0 * INV2PI), n1 = rintf(pj1 * INV2PI);
                float x0 = fmaf(n0, -TWOPI_HI, pj0); x0 = fmaf(n0, -TWOPI_LO, x0);
                float x1 = fmaf(n1, -TWOPI_HI, pj1); x1 = fmaf(n1, -TWOPI_LO, x1);
                float sv0, cv0, sv1, cv1;
                sincosf(x0, &sv0, &cv0);
                sincosf(x1, &sv1, &cv1);
                aF[j >> 1][slotL + rr]       = packh2(sv0, sv1);   // sin: k 0..63
                aF[(j >> 1) + 4][slotL + rr] = packh2(cv0, cv1);   // cos: k 64..127
            }
        }

        float acc[16][4];

        // layer 0 (bias = zb row for image b)
        layer_mma(aF, acc, sbase + OFF_W0, nLoc, bSelKg);
        epi_pack(aF, acc, sZB + b * HID, q);
        // layer 1
        layer_mma(aF, acc, sbase + OFF_W1, nLoc, bSelKg);
        epi_pack(aF, acc, sB1, q);
        // layer 2
        layer_mma(aF, acc, sbase + OFF_W2, nLoc, bSelKg);

        // -------- fused: bias2 + relu + (h @ wout) + reduce + scatter -------
        {
            float o0r0 = 0.f, o1r0 = 0.f, o0r1 = 0.f, o1r1 = 0.f;
            #pragma unroll
            for (int nt = 0; nt < 16; ++nt) {
                int c = 8 * nt + 2 * q;
                float2 bb = *reinterpret_cast<const float2*>(sB2 + c);
                float4 wo = *reinterpret_cast<const float4*>(sWo + c);
                float h0 = fmaxf(acc[nt][0] + bb.x, 0.f);
                float h1 = fmaxf(acc[nt][1] + bb.y, 0.f);
                float h2 = fmaxf(acc[nt][2] + bb.x, 0.f);
                float h3 = fmaxf(acc[nt][3] + bb.y, 0.f);
                o0r0 = fmaf(h0, wo.x, fmaf(h1, wo.z, o0r0));
                o1r0 = fmaf(h0, wo.y, fmaf(h1, wo.w, o1r0));
                o0r1 = fmaf(h2, wo.x, fmaf(h3, wo.z, o0r1));
                o1r1 = fmaf(h2, wo.y, fmaf(h3, wo.w, o1r1));
            }
            o0r0 += __shfl_xor_sync(0xFFFFFFFF, o0r0, 1);
            o0r0 += __shfl_xor_sync(0xFFFFFFFF, o0r0, 2);
            o1r0 += __shfl_xor_sync(0xFFFFFFFF, o1r0, 1);
            o1r0 += __shfl_xor_sync(0xFFFFFFFF, o1r0, 2);
            o0r1 += __shfl_xor_sync(0xFFFFFFFF, o0r1, 1);
            o0r1 += __shfl_xor_sync(0xFFFFFFFF, o0r1, 2);
            o1r1 += __shfl_xor_sync(0xFFFFFFFF, o1r1, 1);
            o1r1 += __shfl_xor_sync(0xFFFFFFFF, o1r1, 2);
            if (q == 0) {
                if (mr0 < M) {
                    int idx = midx[mr0];
                    *reinterpret_cast<float2*>(out + ((size_t)b * NPIX + idx) * 2) =
                        make_float2(o0r0 + bo0, o1r0 + bo1);
                }
                if (mr1 < M) {
                    int idx = midx[mr1];
                    *reinterpret_cast<float2*>(out + ((size_t)b * NPIX + idx) * 2) =
                        make_float2(o0r1 + bo0, o1r1 + bo1);
                }
            }
        }

        unit += gridDim.x;
    }
}

extern "C" void kernel_launch(void* const* d_in, const int* in_sizes, int n_in,
                              void* d_out, int out_size)
{
    const float* z      = (const float*)d_in[0];
    const float* rotmat = (const float*)d_in[1];
    const float* pc     = (const float*)d_in[2];
    const int*   midx   = (const int*)  d_in[3];
    const float* bg     = (const float*)d_in[4];
    const float* w0     = (const float*)d_in[5];
    const float* b0     = (const float*)d_in[6];
    const float* w1     = (const float*)d_in[7];
    const float* b1     = (const float*)d_in[8];
    const float* w2     = (const float*)d_in[9];
    const float* b2     = (const float*)d_in[10];
    const float* wout   = (const float*)d_in[11];
    const float* bout   = (const float*)d_in[12];
    float* out = (float*)d_out;

    const int M = in_sizes[3];
    const int B = in_sizes[0] / ZD;
    const int tiles = (M + TILE_R - 1) / TILE_R;
    const int total = B * tiles;

    // zero whole output (poisoned; only masked pixels are written)
    {
        int n4 = out_size / 4;
        int blocks = (n4 + 255) / 256;
        if (blocks > 2048) blocks = 2048;
        ifv_zero_kernel<<<blocks, 256>>>((float4*)out, n4);
    }

    static bool attr_done = false;
    if (!attr_done) {
        cudaFuncSetAttribute(ifv_reg_kernel,
                             cudaFuncAttributeMaxDynamicSharedMemorySize, SMEM_BYTES);
        attr_done = true;
    }
    int grid = total < GRID_P ? total : GRID_P;
    ifv_reg_kernel<<<grid, NTHREADS, SMEM_BYTES>>>(
        z, rotmat, pc, midx, bg, w0, b0, w1, b1, w2, b2, wout, bout,
        out, M, tiles, total, B);
}